// round 5
// baseline (speedup 1.0000x reference)
#include <cuda_runtime.h>
#include <cuda_bf16.h>

// InnerProduct_541165879452
// lp[r,p] = sum_f w[p,f]^2 * sum_e x[r,f,e]^2
// x: [R=32768, F=64, E=16] f32, w: [P=10, F=64] f32, out: [R,10] f32.
//
// Grid-stride persistent warps (weights loaded+squared ONCE per warp),
// 2-row software pipeline so LDG.128s stay in flight during the shuffle
// reduce of the previous row, split-butterfly reduce (46 SHFLs/row vs 66),
// __ldcs streaming loads for x.

#define F_DIM 64
#define E_DIM 16
#define P_DIM 10
#define ROW_FLOATS (F_DIM * E_DIM)   // 1024 floats = 4 KB per row
#define WARPS_PER_BLOCK 8
#define NUM_BLOCKS 1024              // 8192 warps -> 4 rows per warp at R=32768

__device__ __forceinline__ float4 ldcs4(const float4* p) {
    return __ldcs(p);
}

// Square-accumulate a row's 8 float4s into per-quarter partial sums.
__device__ __forceinline__ void sq_row(const float4 v[8], float s[8]) {
#pragma unroll
    for (int i = 0; i < 8; i++) {
        float t = v[i].x * v[i].x;
        t = fmaf(v[i].y, v[i].y, t);
        t = fmaf(v[i].z, v[i].z, t);
        s[i] = fmaf(v[i].w, v[i].w, t);
    }
}

// Full per-row reduce + store. s[] holds per-quarter sumsq; lane layout:
// quarter j of the row was read by lane with (j & 31); f = 8i + (lane>>2).
__device__ __forceinline__ void reduce_store(float s[8],
                                             const float wa[P_DIM],
                                             const float wb[P_DIM],
                                             int lane, int q,
                                             float* __restrict__ orow) {
    // Quad reduce: lanes {4c..4c+3} share f for every i.
#pragma unroll
    for (int i = 0; i < 8; i++) {
        s[i] += __shfl_xor_sync(0xffffffffu, s[i], 1);
        s[i] += __shfl_xor_sync(0xffffffffu, s[i], 2);
    }

    // Static select of this lane's two owned xsq values (f_a = 16q+c, f_b = f_a+8).
    float xa = (q == 0) ? s[0] : (q == 1) ? s[2] : (q == 2) ? s[4] : s[6];
    float xb = (q == 0) ? s[1] : (q == 1) ? s[3] : (q == 2) ? s[5] : s[7];

    float acc[P_DIM];
#pragma unroll
    for (int p = 0; p < P_DIM; p++)
        acc[p] = fmaf(xa, wa[p], xb * wb[p]);

    // Level 1: xor 16 (10 SHFL). Afterwards lane L and L^16 are identical.
#pragma unroll
    for (int p = 0; p < P_DIM; p++)
        acc[p] += __shfl_xor_sync(0xffffffffu, acc[p], 16);

    // Exploit the redundancy: low half continues with p0..4, high half p5..9.
    const bool hi = (lane & 16) != 0;
    float a2[5];
#pragma unroll
    for (int j = 0; j < 5; j++)
        a2[j] = hi ? acc[j + 5] : acc[j];

    // Levels 2..5 on 5 regs (20 SHFL). Partners stay within each 16-lane half.
#pragma unroll
    for (int off = 8; off >= 1; off >>= 1) {
#pragma unroll
        for (int j = 0; j < 5; j++)
            a2[j] += __shfl_xor_sync(0xffffffffu, a2[j], off);
    }

    // lanes 0..15 all hold p0..4; lanes 16..31 hold p5..9.
    if (lane == 0) {
#pragma unroll
        for (int j = 0; j < 5; j++) orow[j] = a2[j];
    } else if (lane == 16) {
#pragma unroll
        for (int j = 0; j < 5; j++) orow[5 + j] = a2[j];
    }
}

__global__ __launch_bounds__(32 * WARPS_PER_BLOCK)
void ip_kernel(const float* __restrict__ x,
               const float* __restrict__ w,
               float* __restrict__ out,
               int R)
{
    const int lane = threadIdx.x & 31;
    const int wid  = threadIdx.x >> 5;
    const int gw   = blockIdx.x * WARPS_PER_BLOCK + wid;   // global warp id
    const int TW   = gridDim.x * WARPS_PER_BLOCK;          // total warps

    const int c = lane >> 2;   // 0..7
    const int q = lane & 3;    // 0..3
    const int f_a = 16 * q + c;
    const int f_b = f_a + 8;

    // Squared weights: loaded ONCE per warp, amortized over all grid-stride rows.
    float wa[P_DIM], wb[P_DIM];
#pragma unroll
    for (int p = 0; p < P_DIM; p++) {
        float va = __ldg(&w[p * F_DIM + f_a]);
        float vb = __ldg(&w[p * F_DIM + f_b]);
        wa[p] = va * va;
        wb[p] = vb * vb;
    }

    // 2-row software pipeline: while row A reduces, row B's loads are in flight.
    for (int rA = gw; rA < R; rA += 2 * TW) {
        const int rB = rA + TW;
        const bool hasB = rB < R;

        const float4* xrA = reinterpret_cast<const float4*>(x + (size_t)rA * ROW_FLOATS);
        const float4* xrB = reinterpret_cast<const float4*>(
            x + (size_t)(hasB ? rB : rA) * ROW_FLOATS);

        float4 vA[8];
#pragma unroll
        for (int i = 0; i < 8; i++) vA[i] = ldcs4(&xrA[i * 32 + lane]);

        float sA[8];
        sq_row(vA, sA);              // consumes vA; registers free for vB

        float4 vB[8];
        if (hasB) {
#pragma unroll
            for (int i = 0; i < 8; i++) vB[i] = ldcs4(&xrB[i * 32 + lane]);
        }

        // Reduce+store row A while row B's LDGs are in flight.
        reduce_store(sA, wa, wb, lane, q, out + (size_t)rA * P_DIM);

        if (hasB) {
            float sB[8];
            sq_row(vB, sB);
            reduce_store(sB, wa, wb, lane, q, out + (size_t)rB * P_DIM);
        }
    }
}

extern "C" void kernel_launch(void* const* d_in, const int* in_sizes, int n_in,
                              void* d_out, int out_size)
{
    const float* x = (const float*)d_in[0];
    const float* w = (const float*)d_in[1];
    float* out = (float*)d_out;

    const int R = in_sizes[0] / ROW_FLOATS;   // 32768

    ip_kernel<<<NUM_BLOCKS, 32 * WARPS_PER_BLOCK>>>(x, w, out, R);
}

// round 6
// speedup vs baseline: 1.0598x; 1.0598x over previous
#include <cuda_runtime.h>
#include <cuda_bf16.h>

// InnerProduct_541165879452
// lp[r,p] = sum_f w[p,f]^2 * sum_e x[r,f,e]^2
// x: [R=32768, F=64, E=16] f32 (row = 1024 floats = 4 KB), w: [10,64] f32, out: [R,10] f32.
//
// 4 lanes per row, 8 rows per warp. Lane (quad q') streams float4 j = q'+4t,
// so f == t for every lane -> weights are warp-uniform per iteration and come
// from smem via 3 broadcast LDS.128. Each lane fused-accumulates
// acc[p] += wsq[p,t] * sumsq(float4) across the whole row stream; the only
// cross-lane reduction is a 2-level quad shuffle per 8-row tile.

#define F_DIM 64
#define P_DIM 10
#define ROW_FLOATS 1024
#define W_STRIDE 12                    // padded so each f-row = 48B (16B-aligned float4 x3)
#define THREADS 256
#define ROWS_PER_WARP 8
#define ROWS_PER_BLOCK (ROWS_PER_WARP * (THREADS / 32))   // 64

__global__ __launch_bounds__(THREADS)
void ip_kernel(const float* __restrict__ x,
               const float* __restrict__ w,
               float* __restrict__ out,
               int R)
{
    __shared__ float wsq[F_DIM * W_STRIDE];   // [f][p] squared weights, 3 KB

    const int tid = threadIdx.x;

    // Zero (covers the 2 pad slots per f), then fill with squared weights.
    for (int i = tid; i < F_DIM * W_STRIDE; i += THREADS) wsq[i] = 0.0f;
    __syncthreads();
    for (int i = tid; i < P_DIM * F_DIM; i += THREADS) {
        int p = i / F_DIM, f = i % F_DIM;
        float v = w[i];
        wsq[f * W_STRIDE + p] = v * v;
    }
    __syncthreads();

    const int lane = tid & 31;
    const int wid  = tid >> 5;
    const int q    = lane & 3;                       // quarter within the f-block
    const int rloc = lane >> 2;                      // 0..7: row within warp tile
    const int row  = blockIdx.x * ROWS_PER_BLOCK + wid * ROWS_PER_WARP + rloc;
    const int rowc = row < R ? row : (R - 1);        // clamp for safe loads

    // Lane's stream: float4 index q + 4t, t = 0..63  (byte stride 64 per t).
    const float4* __restrict__ xp =
        reinterpret_cast<const float4*>(x + (size_t)rowc * ROW_FLOATS) + q;

    float acc[P_DIM];
#pragma unroll
    for (int p = 0; p < P_DIM; p++) acc[p] = 0.0f;

    for (int tb = 0; tb < 64; tb += 4) {
        // Front-batch 4 independent LDG.128 (MLP = 4 per batch).
        float4 v[4];
#pragma unroll
        for (int u = 0; u < 4; u++)
            v[u] = __ldcs(xp + 4 * (tb + u));

#pragma unroll
        for (int u = 0; u < 4; u++) {
            const int t = tb + u;
            // Warp-uniform broadcast weight row for f = t.
            const float4* wr = reinterpret_cast<const float4*>(wsq + t * W_STRIDE);
            const float4 w0 = wr[0], w1 = wr[1], w2 = wr[2];

            float s = v[u].x * v[u].x;
            s = fmaf(v[u].y, v[u].y, s);
            s = fmaf(v[u].z, v[u].z, s);
            s = fmaf(v[u].w, v[u].w, s);

            acc[0] = fmaf(w0.x, s, acc[0]);
            acc[1] = fmaf(w0.y, s, acc[1]);
            acc[2] = fmaf(w0.z, s, acc[2]);
            acc[3] = fmaf(w0.w, s, acc[3]);
            acc[4] = fmaf(w1.x, s, acc[4]);
            acc[5] = fmaf(w1.y, s, acc[5]);
            acc[6] = fmaf(w1.z, s, acc[6]);
            acc[7] = fmaf(w1.w, s, acc[7]);
            acc[8] = fmaf(w2.x, s, acc[8]);
            acc[9] = fmaf(w2.y, s, acc[9]);
        }
    }

    // Quad reduce: 2 shuffle levels, 20 SHFL per 8 rows total.
#pragma unroll
    for (int p = 0; p < P_DIM; p++)
        acc[p] += __shfl_xor_sync(0xffffffffu, acc[p], 1);
#pragma unroll
    for (int p = 0; p < P_DIM; p++)
        acc[p] += __shfl_xor_sync(0xffffffffu, acc[p], 2);

    // Row byte offset = 40*row -> 8B aligned: 5x STG.64 from quad leader.
    if (q == 0 && row < R) {
        float2* o = reinterpret_cast<float2*>(out + (size_t)row * P_DIM);
#pragma unroll
        for (int j = 0; j < 5; j++)
            o[j] = make_float2(acc[2 * j], acc[2 * j + 1]);
    }
}

extern "C" void kernel_launch(void* const* d_in, const int* in_sizes, int n_in,
                              void* d_out, int out_size)
{
    const float* x = (const float*)d_in[0];
    const float* w = (const float*)d_in[1];
    float* out = (float*)d_out;

    const int R = in_sizes[0] / ROW_FLOATS;                     // 32768
    const int blocks = (R + ROWS_PER_BLOCK - 1) / ROWS_PER_BLOCK;  // 512

    ip_kernel<<<blocks, THREADS>>>(x, w, out, R);
}